// round 14
// baseline (speedup 1.0000x reference)
#include <cuda_runtime.h>
#include <cuda_fp16.h>
#include <math.h>
#include <stdint.h>

// ---------------- problem constants ----------------
#define VV     50257
#define DD     1024
#define KHOT   1024
#define RHOT   768
#define HIDD   1024
#define NFQ    48
#define INDIM  104
#define INDIMP 128
#define NTMAX  2048
#define NCOLD  (VV - KHOT)      // 49233
#define NRMAX  (NTMAX + NCOLD)  // 51281

typedef __half fp16;

// ---------------- device scratch (static; no runtime alloc) ----------------
static __device__ fp16 g_PHIh[(size_t)NRMAX * INDIMP];
static __device__ fp16 g_H1h [(size_t)NRMAX * HIDD];
static __device__ fp16 g_H2h [(size_t)NRMAX * HIDD];
static __device__ fp16 g_Eh  [(size_t)KHOT * DD];
static __device__ fp16 g_CTh [(size_t)NTMAX * DD];
static __device__ fp16 g_LATh[(size_t)NTMAX * DD];
static __device__ fp16 g_LWh [(size_t)NTMAX * DD];
static __device__ fp16 g_WT1h[(size_t)HIDD * INDIMP];
static __device__ fp16 g_WT2h[(size_t)HIDD * HIDD];
static __device__ fp16 g_WT3h[(size_t)DD * HIDD];   // W3^T  [D][HID]
static __device__ fp16 g_W3Dh[(size_t)HIDD * DD];   // W3 direct [HID][D]
static __device__ fp16 g_BTh [(size_t)DD * RHOT];
static __device__ fp16 g_Uh  [(size_t)KHOT * RHOT];
static __device__ float g_CB3[NTMAX];

// ---------------- static streams/events (created at load; no device mem) ---
static cudaStream_t g_s1;
static cudaEvent_t  g_evA, g_evE, g_evH1, g_evB, g_evL, g_evHot, g_evW3;
static struct _AsyncInit {
    _AsyncInit() {
        cudaStreamCreateWithFlags(&g_s1, cudaStreamNonBlocking);
        cudaEventCreateWithFlags(&g_evA,   cudaEventDisableTiming);
        cudaEventCreateWithFlags(&g_evE,   cudaEventDisableTiming);
        cudaEventCreateWithFlags(&g_evH1,  cudaEventDisableTiming);
        cudaEventCreateWithFlags(&g_evB,   cudaEventDisableTiming);
        cudaEventCreateWithFlags(&g_evL,   cudaEventDisableTiming);
        cudaEventCreateWithFlags(&g_evHot, cudaEventDisableTiming);
        cudaEventCreateWithFlags(&g_evW3,  cudaEventDisableTiming);
    }
} g_asyncInit;

// ---------------- helpers ----------------
__device__ __forceinline__ void hsplit(float x, fp16& h, fp16& l) {
    h = __float2half_rn(x);
    l = __float2half_rn(x - __half2float(h));
}
__device__ __forceinline__ float gelu_exact(float x) {
    return 0.5f * x * (1.0f + erff(x * 0.7071067811865476f));
}
__device__ __forceinline__ uint32_t s2u(const void* p) {
    uint32_t a;
    asm("{ .reg .u64 t; cvta.to.shared.u64 t, %1; cvt.u32.u64 %0, t; }" : "=r"(a) : "l"(p));
    return a;
}
__device__ __forceinline__ void ldsm4(uint32_t* r, uint32_t addr) {
    asm volatile("ldmatrix.sync.aligned.m8n8.x4.shared.b16 {%0,%1,%2,%3}, [%4];"
                 : "=r"(r[0]), "=r"(r[1]), "=r"(r[2]), "=r"(r[3]) : "r"(addr));
}
__device__ __forceinline__ void mma16816(float* c, const uint32_t* a, const uint32_t* b) {
    asm volatile("mma.sync.aligned.m16n8k16.row.col.f32.f16.f16.f32 "
                 "{%0,%1,%2,%3}, {%4,%5,%6,%7}, {%8,%9}, {%0,%1,%2,%3};"
                 : "+f"(c[0]), "+f"(c[1]), "+f"(c[2]), "+f"(c[3])
                 : "r"(a[0]), "r"(a[1]), "r"(a[2]), "r"(a[3]), "r"(b[0]), "r"(b[1]));
}
__device__ __forceinline__ void cpa16(uint32_t dst, const void* src) {
    asm volatile("cp.async.cg.shared.global [%0], [%1], 16;" :: "r"(dst), "l"(src) : "memory");
}

// ---------------- SMEM geometry ----------------
#define ROWB   80
#define A_ROWS 128
#define B_ROWS 128
#define NSTG   3

// ---------------- the mma.sync GEMM (BM=128, BN=128, BK=32, occ 2) ---------
// PASSES: 1 = ah*bh; 2 = + al*bh (A split).
// MODE 0/1/2: C hi plane (+lo for rows < loRows)
// MODE 3: out[gm, colmap[gn]] = acc * exp(*pLA) + out_bias[v]
// MODE 4: out[gm, colmap[gn]] = (acc + rowc[gm]) * exp(*pLA)*(*pTG) + out_bias[v]
template<int MODE, bool SWAPXY, int PASSES>
__global__ void __launch_bounds__(256, 2)
mma_gemm(const fp16* __restrict__ Ah, const fp16* __restrict__ Al, int lda,
         const fp16* __restrict__ Bh, int ldb, int browOff,
         int M, int N, int KT,
         const float* __restrict__ bias, const float* __restrict__ pTG,
         const float* __restrict__ pLA, const float* __restrict__ rowc,
         const int* __restrict__ colmap,
         float* __restrict__ outF, const float* __restrict__ out_bias,
         fp16* __restrict__ Chi, fp16* __restrict__ Clo, int ldc, int loRows)
{
    constexpr int AR = (PASSES >= 2) ? 2 * A_ROWS : A_ROWS;
    constexpr int BR = B_ROWS;
    constexpr int STAGE = (AR + BR) * ROWB;
    constexpr int CH = (AR + BR) / 64;
    constexpr int O_AL = A_ROWS * ROWB;
    constexpr int O_BH = AR * ROWB;

    extern __shared__ char smem[];
    const uint32_t sbase = s2u(smem);
    const int tid = threadIdx.x;
    const int bm = (SWAPXY ? blockIdx.x : blockIdx.y) << 7;
    const int bn = (SWAPXY ? blockIdx.y : blockIdx.x) << 7;

    float acc[2][8][4];
    #pragma unroll
    for (int i = 0; i < 2; i++)
        #pragma unroll
        for (int j = 0; j < 8; j++)
            #pragma unroll
            for (int q = 0; q < 4; q++) acc[i][j][q] = 0.f;

    auto load_stage = [&](int s, int kt) {
        const int k0 = kt << 5;
        const uint32_t stg = sbase + s * STAGE;
        #pragma unroll
        for (int i = 0; i < CH; i++) {
            int idx = tid + (i << 8);
            int row = idx >> 2;
            int seg = idx & 3;
            uint32_t daddr = stg + row * ROWB + (seg << 4);
            const fp16* src;
            bool valid;
            if (row < AR) {
                int plane = (PASSES >= 2) ? (row >> 7) : 0;
                int r = row & (A_ROWS - 1);
                int gm = bm + r;
                valid = gm < M;
                src = (plane ? Al : Ah) + (size_t)gm * lda + k0 + (seg << 3);
            } else {
                int r = row - AR;
                int gn = bn + r;
                valid = gn < N;
                src = Bh + (size_t)(gn + browOff) * ldb + k0 + (seg << 3);
            }
            if (valid) cpa16(daddr, src);
            else {
                asm volatile("st.shared.v4.b32 [%0], {%1,%1,%1,%1};" :: "r"(daddr), "r"(0u) : "memory");
            }
        }
        asm volatile("cp.async.commit_group;" ::: "memory");
    };

    const int lane = tid & 31, wid = tid >> 5;
    const int wm = wid & 3;        // 4 M-subtiles of 32
    const int wn = wid >> 2;       // 2 N-subtiles of 64

    load_stage(0, 0);
    if (KT > 1) load_stage(1, 1);

    for (int kt = 0; kt < KT; kt++) {
        int s = kt % NSTG;
        if (kt + 1 < KT) asm volatile("cp.async.wait_group 1;" ::: "memory");
        else             asm volatile("cp.async.wait_group 0;" ::: "memory");
        __syncthreads();
        if (kt + 2 < KT) load_stage((kt + 2) % NSTG, kt + 2);

        const uint32_t stg = sbase + s * STAGE;
        #pragma unroll
        for (int kk = 0; kk < 2; kk++) {
            uint32_t bh[8][2];
            #pragma unroll
            for (int bi = 0; bi < 4; bi++) {
                int row = wn * 64 + bi * 16 + (lane & 7) + ((lane >> 4) << 3);
                int kb  = kk * 16 + (((lane >> 3) & 1) << 3);
                uint32_t bd = stg + O_BH + row * ROWB + kb * 2;
                uint32_t t[4];
                ldsm4(t, bd);
                bh[bi*2][0] = t[0]; bh[bi*2][1] = t[1];
                bh[bi*2+1][0] = t[2]; bh[bi*2+1][1] = t[3];
            }
            #pragma unroll
            for (int mi = 0; mi < 2; mi++) {
                int row = wm * 32 + mi * 16 + (lane & 15);
                int kb  = kk * 16 + ((lane >> 4) << 3);
                uint32_t ad = stg + row * ROWB + kb * 2;
                uint32_t ah[4], al[4];
                ldsm4(ah, ad);
                if (PASSES >= 2) ldsm4(al, ad + O_AL);
                #pragma unroll
                for (int ni = 0; ni < 8; ni++) {
                    mma16816(acc[mi][ni], ah, bh[ni]);
                    if (PASSES >= 2) mma16816(acc[mi][ni], al, bh[ni]);
                }
            }
        }
        __syncthreads();
    }

    // ---------------- epilogue ----------------
    float s1 = 1.f;
    if (MODE == 2) s1 = *pTG;
    if (MODE == 3) s1 = expf(*pLA);
    if (MODE == 4) s1 = expf(*pLA) * (*pTG);

    #pragma unroll
    for (int mi = 0; mi < 2; mi++) {
        #pragma unroll
        for (int ni = 0; ni < 8; ni++) {
            int gm0 = bm + wm * 32 + mi * 16 + (lane >> 2);
            int gn0 = bn + wn * 64 + ni * 8 + ((lane & 3) << 1);
            #pragma unroll
            for (int h = 0; h < 2; h++) {
                int gm = gm0 + h * 8;
                if (gm >= M) continue;
                float v0 = acc[mi][ni][h * 2 + 0];
                float v1 = acc[mi][ni][h * 2 + 1];
                if (MODE <= 2) {
                    if (gn0 >= N) continue;
                    if (MODE == 1) {
                        v0 = gelu_exact(v0 + bias[gn0]);
                        v1 = gelu_exact(v1 + bias[gn0 + 1]);
                    } else if (MODE == 2) {
                        v0 = (v0 + bias[gn0]) * s1;
                        v1 = (v1 + bias[gn0 + 1]) * s1;
                    }
                    fp16 h0, l0, h1, l1;
                    hsplit(v0, h0, l0); hsplit(v1, h1, l1);
                    size_t off = (size_t)gm * ldc + gn0;
                    *(__half2*)(Chi + off) = __halves2half2(h0, h1);
                    if (gm < loRows)
                        *(__half2*)(Clo + off) = __halves2half2(l0, l1);
                } else {
                    float rc = (MODE == 4) ? rowc[gm] : 0.f;
                    if (gn0 < N) {
                        int v = colmap[gn0];
                        v = v < 0 ? 0 : (v > VV - 1 ? VV - 1 : v);
                        outF[(size_t)gm * VV + v] = (v0 + rc) * s1 + out_bias[v];
                    }
                    if (gn0 + 1 < N) {
                        int v = colmap[gn0 + 1];
                        v = v < 0 ? 0 : (v > VV - 1 ? VV - 1 : v);
                        outF[(size_t)gm * VV + v] = (v1 + rc) * s1 + out_bias[v];
                    }
                }
            }
        }
    }
}

// ---------------- prep kernels ----------------
__global__ void phi_kernel(const int* __restrict__ tokens, const int* __restrict__ n2o,
                           const float* __restrict__ freqs, int NT, int nrows)
{
    int idx = blockIdx.x * blockDim.x + threadIdx.x;
    if (idx >= nrows * INDIMP) return;
    int row = idx >> 7;
    int f = idx & 127;
    int id = (row < NT) ? tokens[row] : n2o[KHOT + (row - NT)];
    float out = 0.f;
    if (f < 2 * NFQ) {
        float x = (float)id / (float)VV;
        int k = (f < NFQ) ? f : f - NFQ;
        float th = x * freqs[k];
        out = (f < NFQ) ? sinf(th) : cosf(th);
    } else if (f < INDIM) {
        int k = f - 2 * NFQ;
        out = (float)((id >> (2 * k)) & 3) / 3.0f;
    }
    g_PHIh[idx] = __float2half_rn(out);
}

__global__ void transT_kernel(const float* __restrict__ W, fp16* __restrict__ oh,
                              int K, int N, int Kpad)
{
    __shared__ float tile[32][33];
    int kb = blockIdx.y << 5, nb = blockIdx.x << 5;
    int tx = threadIdx.x & 31, ty = threadIdx.x >> 5;
    #pragma unroll
    for (int i = ty; i < 32; i += 8) {
        int k = kb + i, n = nb + tx;
        tile[i][tx] = (k < K && n < N) ? W[(size_t)k * N + n] : 0.f;
    }
    __syncthreads();
    #pragma unroll
    for (int i = ty; i < 32; i += 8) {
        int n = nb + i, k = kb + tx;
        if (n < N && k < Kpad)
            oh[(size_t)n * Kpad + k] = __float2half_rn(tile[tx][i]);
    }
}

__global__ void convD_kernel(const float* __restrict__ src, fp16* __restrict__ oh, int n)
{
    int idx = blockIdx.x * blockDim.x + threadIdx.x;
    if (idx >= n) return;
    oh[idx] = __float2half_rn(src[idx]);
}

// latent select (hi plane) + per-row b3 dot. One block per token row.
__global__ void latent_cb3_kernel(const int* __restrict__ tokens, const int* __restrict__ o2n,
                                  const float* __restrict__ b3, int NT)
{
    __shared__ float red[8];
    int t = blockIdx.x;
    int nt = o2n[tokens[t]];
    int j = nt < 0 ? 0 : (nt > KHOT - 1 ? KHOT - 1 : nt);
    bool hot = (nt < KHOT);
    float s = 0.f;
    for (int d = threadIdx.x; d < DD; d += 256) {
        size_t o = (size_t)t * DD + d;
        fp16 vh = hot ? g_Eh[(size_t)j * DD + d] : g_CTh[o];
        g_LATh[o] = vh;
        s += __half2float(vh) * b3[d];
    }
    #pragma unroll
    for (int off = 16; off; off >>= 1) s += __shfl_down_sync(0xFFFFFFFFu, s, off);
    if ((threadIdx.x & 31) == 0) red[threadIdx.x >> 5] = s;
    __syncthreads();
    if (threadIdx.x == 0) {
        float tot = 0.f;
        #pragma unroll
        for (int i = 0; i < 8; i++) tot += red[i];
        g_CB3[t] = tot;
    }
}

// ---------------- launch ----------------
static inline int smemFor(int P) {
    int ar = (P >= 2) ? 2 * A_ROWS : A_ROWS;
    return NSTG * (ar + B_ROWS) * ROWB;
}

extern "C" void kernel_launch(void* const* d_in, const int* in_sizes, int n_in,
                              void* d_out, int out_size)
{
    const int*   tokens   = (const int*)  d_in[0];
    const int*   o2n      = (const int*)  d_in[1];
    const int*   n2o      = (const int*)  d_in[2];
    const float* freqs    = (const float*)d_in[3];
    const float* U        = (const float*)d_in[4];
    const float* Bm       = (const float*)d_in[5];
    const float* W1       = (const float*)d_in[6];
    const float* b1       = (const float*)d_in[7];
    const float* W2       = (const float*)d_in[8];
    const float* b2       = (const float*)d_in[9];
    const float* W3       = (const float*)d_in[10];
    const float* b3       = (const float*)d_in[11];
    const float* tg       = (const float*)d_in[12];
    const float* la       = (const float*)d_in[13];
    const float* out_bias = (const float*)d_in[14];
    float* out = (float*)d_out;

    int NT = in_sizes[0];
    if (NT > NTMAX) NT = NTMAX;
    if (NT <= 0) return;
    int nrows = NT + NCOLD;

    fp16 *pPHIh,*pH1h,*pH2h,*pEh,*pCTh,*pLATh,*pLWh;
    fp16 *pWT1h,*pWT2h,*pWT3h,*pW3Dh,*pBTh,*pUh;
    float *pCB3;
    cudaGetSymbolAddress((void**)&pPHIh, g_PHIh);
    cudaGetSymbolAddress((void**)&pH1h,  g_H1h);
    cudaGetSymbolAddress((void**)&pH2h,  g_H2h);
    cudaGetSymbolAddress((void**)&pEh,   g_Eh);
    cudaGetSymbolAddress((void**)&pCTh,  g_CTh);
    cudaGetSymbolAddress((void**)&pLATh, g_LATh);
    cudaGetSymbolAddress((void**)&pLWh,  g_LWh);
    cudaGetSymbolAddress((void**)&pWT1h, g_WT1h);
    cudaGetSymbolAddress((void**)&pWT2h, g_WT2h);
    cudaGetSymbolAddress((void**)&pWT3h, g_WT3h);
    cudaGetSymbolAddress((void**)&pW3Dh, g_W3Dh);
    cudaGetSymbolAddress((void**)&pBTh,  g_BTh);
    cudaGetSymbolAddress((void**)&pUh,   g_Uh);
    cudaGetSymbolAddress((void**)&pCB3,  g_CB3);

    cudaFuncSetAttribute(mma_gemm<1,false,1>, cudaFuncAttributeMaxDynamicSharedMemorySize, smemFor(1));
    cudaFuncSetAttribute(mma_gemm<2,false,1>, cudaFuncAttributeMaxDynamicSharedMemorySize, smemFor(1));
    cudaFuncSetAttribute(mma_gemm<0,false,1>, cudaFuncAttributeMaxDynamicSharedMemorySize, smemFor(1));
    cudaFuncSetAttribute(mma_gemm<3,true ,1>, cudaFuncAttributeMaxDynamicSharedMemorySize, smemFor(1));
    cudaFuncSetAttribute(mma_gemm<4,true ,1>, cudaFuncAttributeMaxDynamicSharedMemorySize, smemFor(1));

    int mtilesCold = (NCOLD + 127) / 128;
    int ttiles = (NT + 127) / 128;

    // ---- side stream: U/B conversion + Ehot (1-pass) + W2T/W3T/W3D ----
    cudaEventRecord(g_evA, 0);
    cudaStreamWaitEvent(g_s1, g_evA, 0);
    convD_kernel<<<(KHOT * RHOT + 255) / 256, 256, 0, g_s1>>>(U, pUh, KHOT * RHOT);
    {
        dim3 g4((DD + 31) / 32, (RHOT + 31) / 32);
        transT_kernel<<<g4, 256, 0, g_s1>>>(Bm, pBTh, RHOT, DD, RHOT);
    }
    {
        dim3 g(DD / 128, KHOT / 128);
        mma_gemm<0,false,1><<<g, 256, smemFor(1), g_s1>>>(pUh, nullptr, RHOT, pBTh, RHOT, 0,
            KHOT, DD, RHOT / 32, nullptr, nullptr, nullptr, nullptr, nullptr,
            nullptr, nullptr, pEh, nullptr, DD, 0);
    }
    cudaEventRecord(g_evE, g_s1);
    {
        dim3 g2((HIDD + 31) / 32, (HIDD + 31) / 32);
        transT_kernel<<<g2, 256, 0, g_s1>>>(W2, pWT2h, HIDD, HIDD, HIDD);
        dim3 g3((DD + 31) / 32, (HIDD + 31) / 32);
        transT_kernel<<<g3, 256, 0, g_s1>>>(W3, pWT3h, HIDD, DD, HIDD);
        convD_kernel<<<(HIDD * DD + 255) / 256, 256, 0, g_s1>>>(W3, pW3Dh, HIDD * DD);
    }
    cudaEventRecord(g_evW3, g_s1);

    // ---- main: minimal prefix -> H1 (cold rows first, then token rows) ----
    phi_kernel<<<(nrows * INDIMP + 255) / 256, 256>>>(tokens, n2o, freqs, NT, nrows);
    {
        dim3 g1((HIDD + 31) / 32, (INDIMP + 31) / 32);
        transT_kernel<<<g1, 256>>>(W1, pWT1h, INDIM, HIDD, INDIMP);
    }
    {
        dim3 g(HIDD / 128, mtilesCold);
        mma_gemm<1,false,1><<<g, 256, smemFor(1)>>>(pPHIh + (size_t)NT * INDIMP, nullptr, INDIMP,
            pWT1h, INDIMP, 0,
            NCOLD, HIDD, INDIMP / 32, b1, nullptr, nullptr, nullptr, nullptr,
            nullptr, nullptr, pH1h + (size_t)NT * HIDD, nullptr, HIDD, 0);
    }

    // ---- fork: H2cold on side stream (right after H1cold) ----
    cudaEventRecord(g_evH1, 0);
    cudaStreamWaitEvent(g_s1, g_evH1, 0);
    {
        dim3 g(HIDD / 128, mtilesCold);
        mma_gemm<1,false,1><<<g, 256, smemFor(1), g_s1>>>(pH1h + (size_t)NT * HIDD, nullptr, HIDD,
            pWT2h, HIDD, 0,
            NCOLD, HIDD, HIDD / 32, b2, nullptr, nullptr, nullptr, nullptr,
            nullptr, nullptr, pH2h + (size_t)NT * HIDD, nullptr, HIDD, 0);
    }
    cudaEventRecord(g_evB, g_s1);

    // ---- main: token chain (hidden under H2cold) ----
    {
        dim3 g(HIDD / 128, ttiles);
        mma_gemm<1,false,1><<<g, 256, smemFor(1)>>>(pPHIh, nullptr, INDIMP, pWT1h, INDIMP, 0,
            NT, HIDD, INDIMP / 32, b1, nullptr, nullptr, nullptr, nullptr,
            nullptr, nullptr, pH1h, nullptr, HIDD, 0);
    }
    cudaStreamWaitEvent(0, g_evW3, 0);
    {
        dim3 g(HIDD / 128, ttiles);
        mma_gemm<1,false,1><<<g, 256, smemFor(1)>>>(pH1h, nullptr, HIDD, pWT2h, HIDD, 0,
            NT, HIDD, HIDD / 32, b2, nullptr, nullptr, nullptr, nullptr,
            nullptr, nullptr, pH2h, nullptr, HIDD, 0);
    }
    {
        dim3 g(DD / 128, ttiles);
        mma_gemm<2,false,1><<<g, 256, smemFor(1)>>>(pH2h, nullptr, HIDD, pWT3h, HIDD, 0,
            NT, DD, HIDD / 32, b3, tg, nullptr, nullptr, nullptr,
            nullptr, nullptr, pCTh, nullptr, DD, 0);
    }
    cudaStreamWaitEvent(0, g_evE, 0);
    latent_cb3_kernel<<<NT, 256>>>(tokens, o2n, b3, NT);
    cudaEventRecord(g_evL, 0);
    // LW3 = latent @ W3^T (1-pass)
    {
        dim3 g(HIDD / 128, ttiles);
        mma_gemm<0,false,1><<<g, 256, smemFor(1)>>>(pLATh, nullptr, DD, pW3Dh, DD, 0,
            NT, HIDD, DD / 32, nullptr, nullptr, nullptr, nullptr, nullptr,
            nullptr, nullptr, pLWh, nullptr, HIDD, 0);
    }
    // ---- hot logits on side stream (overlaps cold logits; disjoint columns) ----
    cudaStreamWaitEvent(g_s1, g_evL, 0);
    {
        dim3 g(ttiles, KHOT / 128);
        mma_gemm<3,true,1><<<g, 256, smemFor(1), g_s1>>>(pLATh, nullptr, DD, pEh, DD, 0,
            NT, KHOT, DD / 32, nullptr, nullptr, la, nullptr, n2o,
            out, out_bias, nullptr, nullptr, 0, 0);
    }
    cudaEventRecord(g_evHot, g_s1);

    // ---- join: cold logits (fp32-acc; dominant) ----
    cudaStreamWaitEvent(0, g_evB, 0);
    {
        dim3 g(ttiles, (NCOLD + 127) / 128);
        mma_gemm<4,true,1><<<g, 256, smemFor(1)>>>(pLWh, nullptr, HIDD, pH2h, HIDD, NT,
            NT, NCOLD, HIDD / 32, nullptr, tg, la, pCB3, n2o + KHOT,
            out, out_bias, nullptr, nullptr, 0, 0);
    }
    cudaStreamWaitEvent(0, g_evHot, 0);
}

// round 15
// speedup vs baseline: 1.0164x; 1.0164x over previous
#include <cuda_runtime.h>
#include <cuda_fp16.h>
#include <math.h>
#include <stdint.h>

// ---------------- problem constants ----------------
#define VV     50257
#define DD     1024
#define KHOT   1024
#define RHOT   768
#define HIDD   1024
#define NFQ    48
#define INDIM  104
#define INDIMP 128
#define NTMAX  2048
#define NCOLD  (VV - KHOT)      // 49233
#define NRMAX  (NTMAX + NCOLD)  // 51281

typedef __half fp16;

// ---------------- device scratch (static; no runtime alloc) ----------------
static __device__ fp16 g_PHIh[(size_t)NRMAX * INDIMP];
static __device__ fp16 g_H1h [(size_t)NRMAX * HIDD];
static __device__ fp16 g_H2h [(size_t)NRMAX * HIDD];
static __device__ fp16 g_Eh  [(size_t)KHOT * DD];
static __device__ fp16 g_CTh [(size_t)NTMAX * DD];
static __device__ fp16 g_LATh[(size_t)NTMAX * DD];
static __device__ fp16 g_LWh [(size_t)NTMAX * DD];
static __device__ fp16 g_WT1h[(size_t)HIDD * INDIMP];
static __device__ fp16 g_WT2h[(size_t)HIDD * HIDD];
static __device__ fp16 g_WT3h[(size_t)DD * HIDD];   // W3^T  [D][HID]
static __device__ fp16 g_W3Dh[(size_t)HIDD * DD];   // W3 direct [HID][D]
static __device__ fp16 g_BTh [(size_t)DD * RHOT];
static __device__ fp16 g_Uh  [(size_t)KHOT * RHOT];
static __device__ float g_CB3[NTMAX];

// ---------------- static streams/events (created at load; no device mem) ---
static cudaStream_t g_s1;
static cudaEvent_t  g_evA, g_evE, g_evH1, g_evB, g_evL, g_evHot, g_evW3;
static struct _AsyncInit {
    _AsyncInit() {
        cudaStreamCreateWithFlags(&g_s1, cudaStreamNonBlocking);
        cudaEventCreateWithFlags(&g_evA,   cudaEventDisableTiming);
        cudaEventCreateWithFlags(&g_evE,   cudaEventDisableTiming);
        cudaEventCreateWithFlags(&g_evH1,  cudaEventDisableTiming);
        cudaEventCreateWithFlags(&g_evB,   cudaEventDisableTiming);
        cudaEventCreateWithFlags(&g_evL,   cudaEventDisableTiming);
        cudaEventCreateWithFlags(&g_evHot, cudaEventDisableTiming);
        cudaEventCreateWithFlags(&g_evW3,  cudaEventDisableTiming);
    }
} g_asyncInit;

// ---------------- helpers ----------------
__device__ __forceinline__ void hsplit(float x, fp16& h, fp16& l) {
    h = __float2half_rn(x);
    l = __float2half_rn(x - __half2float(h));
}
__device__ __forceinline__ float gelu_exact(float x) {
    return 0.5f * x * (1.0f + erff(x * 0.7071067811865476f));
}
__device__ __forceinline__ uint32_t s2u(const void* p) {
    uint32_t a;
    asm("{ .reg .u64 t; cvta.to.shared.u64 t, %1; cvt.u32.u64 %0, t; }" : "=r"(a) : "l"(p));
    return a;
}
__device__ __forceinline__ void ldsm4(uint32_t* r, uint32_t addr) {
    asm volatile("ldmatrix.sync.aligned.m8n8.x4.shared.b16 {%0,%1,%2,%3}, [%4];"
                 : "=r"(r[0]), "=r"(r[1]), "=r"(r[2]), "=r"(r[3]) : "r"(addr));
}
__device__ __forceinline__ void mma16816(float* c, const uint32_t* a, const uint32_t* b) {
    asm volatile("mma.sync.aligned.m16n8k16.row.col.f32.f16.f16.f32 "
                 "{%0,%1,%2,%3}, {%4,%5,%6,%7}, {%8,%9}, {%0,%1,%2,%3};"
                 : "+f"(c[0]), "+f"(c[1]), "+f"(c[2]), "+f"(c[3])
                 : "r"(a[0]), "r"(a[1]), "r"(a[2]), "r"(a[3]), "r"(b[0]), "r"(b[1]));
}
__device__ __forceinline__ void cpa16(uint32_t dst, const void* src) {
    asm volatile("cp.async.cg.shared.global [%0], [%1], 16;" :: "r"(dst), "l"(src) : "memory");
}

// ---------------- SMEM geometry ----------------
#define ROWB   80
#define A_ROWS 128
#define B_ROWS 128
#define NSTG   3

// ---------------- the mma.sync GEMM (BM=128, BN=128, BK=32, occ 2) ---------
// PASSES: 1 = ah*bh; 2 = + al*bh (A split).
// MODE 0/1/2: C hi plane (+lo for rows < loRows)
// MODE 3: out[gm, colmap[gn]] = acc * exp(*pLA) + out_bias[v]
// MODE 4: out[gm, colmap[gn]] = (acc + rowc[gm]) * exp(*pLA)*(*pTG) + out_bias[v]
template<int MODE, bool SWAPXY, int PASSES>
__global__ void __launch_bounds__(256, 2)
mma_gemm(const fp16* __restrict__ Ah, const fp16* __restrict__ Al, int lda,
         const fp16* __restrict__ Bh, int ldb, int browOff,
         int M, int N, int KT,
         const float* __restrict__ bias, const float* __restrict__ pTG,
         const float* __restrict__ pLA, const float* __restrict__ rowc,
         const int* __restrict__ colmap,
         float* __restrict__ outF, const float* __restrict__ out_bias,
         fp16* __restrict__ Chi, fp16* __restrict__ Clo, int ldc, int loRows)
{
    constexpr int AR = (PASSES >= 2) ? 2 * A_ROWS : A_ROWS;
    constexpr int BR = B_ROWS;
    constexpr int STAGE = (AR + BR) * ROWB;
    constexpr int CH = (AR + BR) / 64;
    constexpr int O_AL = A_ROWS * ROWB;
    constexpr int O_BH = AR * ROWB;

    extern __shared__ char smem[];
    const uint32_t sbase = s2u(smem);
    const int tid = threadIdx.x;
    const int bm = (SWAPXY ? blockIdx.x : blockIdx.y) << 7;
    const int bn = (SWAPXY ? blockIdx.y : blockIdx.x) << 7;

    float acc[2][8][4];
    #pragma unroll
    for (int i = 0; i < 2; i++)
        #pragma unroll
        for (int j = 0; j < 8; j++)
            #pragma unroll
            for (int q = 0; q < 4; q++) acc[i][j][q] = 0.f;

    auto load_stage = [&](int s, int kt) {
        const int k0 = kt << 5;
        const uint32_t stg = sbase + s * STAGE;
        #pragma unroll
        for (int i = 0; i < CH; i++) {
            int idx = tid + (i << 8);
            int row = idx >> 2;
            int seg = idx & 3;
            uint32_t daddr = stg + row * ROWB + (seg << 4);
            const fp16* src;
            bool valid;
            if (row < AR) {
                int plane = (PASSES >= 2) ? (row >> 7) : 0;
                int r = row & (A_ROWS - 1);
                int gm = bm + r;
                valid = gm < M;
                src = (plane ? Al : Ah) + (size_t)gm * lda + k0 + (seg << 3);
            } else {
                int r = row - AR;
                int gn = bn + r;
                valid = gn < N;
                src = Bh + (size_t)(gn + browOff) * ldb + k0 + (seg << 3);
            }
            if (valid) cpa16(daddr, src);
            else {
                asm volatile("st.shared.v4.b32 [%0], {%1,%1,%1,%1};" :: "r"(daddr), "r"(0u) : "memory");
            }
        }
        asm volatile("cp.async.commit_group;" ::: "memory");
    };

    const int lane = tid & 31, wid = tid >> 5;
    const int wm = wid & 3;        // 4 M-subtiles of 32
    const int wn = wid >> 2;       // 2 N-subtiles of 64

    load_stage(0, 0);
    if (KT > 1) load_stage(1, 1);

    for (int kt = 0; kt < KT; kt++) {
        int s = kt % NSTG;
        if (kt + 1 < KT) asm volatile("cp.async.wait_group 1;" ::: "memory");
        else             asm volatile("cp.async.wait_group 0;" ::: "memory");
        __syncthreads();
        if (kt + 2 < KT) load_stage((kt + 2) % NSTG, kt + 2);

        const uint32_t stg = sbase + s * STAGE;
        #pragma unroll
        for (int kk = 0; kk < 2; kk++) {
            uint32_t bh[8][2];
            #pragma unroll
            for (int bi = 0; bi < 4; bi++) {
                int row = wn * 64 + bi * 16 + (lane & 7) + ((lane >> 4) << 3);
                int kb  = kk * 16 + (((lane >> 3) & 1) << 3);
                uint32_t bd = stg + O_BH + row * ROWB + kb * 2;
                uint32_t t[4];
                ldsm4(t, bd);
                bh[bi*2][0] = t[0]; bh[bi*2][1] = t[1];
                bh[bi*2+1][0] = t[2]; bh[bi*2+1][1] = t[3];
            }
            #pragma unroll
            for (int mi = 0; mi < 2; mi++) {
                int row = wm * 32 + mi * 16 + (lane & 15);
                int kb  = kk * 16 + ((lane >> 4) << 3);
                uint32_t ad = stg + row * ROWB + kb * 2;
                uint32_t ah[4], al[4];
                ldsm4(ah, ad);
                if (PASSES >= 2) ldsm4(al, ad + O_AL);
                #pragma unroll
                for (int ni = 0; ni < 8; ni++) {
                    mma16816(acc[mi][ni], ah, bh[ni]);
                    if (PASSES >= 2) mma16816(acc[mi][ni], al, bh[ni]);
                }
            }
        }
        __syncthreads();
    }

    // ---------------- epilogue ----------------
    float s1 = 1.f;
    if (MODE == 2) s1 = *pTG;
    if (MODE == 3) s1 = expf(*pLA);
    if (MODE == 4) s1 = expf(*pLA) * (*pTG);

    #pragma unroll
    for (int mi = 0; mi < 2; mi++) {
        #pragma unroll
        for (int ni = 0; ni < 8; ni++) {
            int gm0 = bm + wm * 32 + mi * 16 + (lane >> 2);
            int gn0 = bn + wn * 64 + ni * 8 + ((lane & 3) << 1);
            #pragma unroll
            for (int h = 0; h < 2; h++) {
                int gm = gm0 + h * 8;
                if (gm >= M) continue;
                float v0 = acc[mi][ni][h * 2 + 0];
                float v1 = acc[mi][ni][h * 2 + 1];
                if (MODE <= 2) {
                    if (gn0 >= N) continue;
                    if (MODE == 1) {
                        v0 = gelu_exact(v0 + bias[gn0]);
                        v1 = gelu_exact(v1 + bias[gn0 + 1]);
                    } else if (MODE == 2) {
                        v0 = (v0 + bias[gn0]) * s1;
                        v1 = (v1 + bias[gn0 + 1]) * s1;
                    }
                    fp16 h0, l0, h1, l1;
                    hsplit(v0, h0, l0); hsplit(v1, h1, l1);
                    size_t off = (size_t)gm * ldc + gn0;
                    *(__half2*)(Chi + off) = __halves2half2(h0, h1);
                    if (gm < loRows)
                        *(__half2*)(Clo + off) = __halves2half2(l0, l1);
                } else {
                    float rc = (MODE == 4) ? rowc[gm] : 0.f;
                    if (gn0 < N) {
                        int v = colmap[gn0];
                        v = v < 0 ? 0 : (v > VV - 1 ? VV - 1 : v);
                        outF[(size_t)gm * VV + v] = (v0 + rc) * s1 + out_bias[v];
                    }
                    if (gn0 + 1 < N) {
                        int v = colmap[gn0 + 1];
                        v = v < 0 ? 0 : (v > VV - 1 ? VV - 1 : v);
                        outF[(size_t)gm * VV + v] = (v1 + rc) * s1 + out_bias[v];
                    }
                }
            }
        }
    }
}

// ---------------- prep kernels ----------------
__global__ void phi_kernel(const int* __restrict__ tokens, const int* __restrict__ n2o,
                           const float* __restrict__ freqs, int NT, int nrows)
{
    int idx = blockIdx.x * blockDim.x + threadIdx.x;
    if (idx >= nrows * INDIMP) return;
    int row = idx >> 7;
    int f = idx & 127;
    int id = (row < NT) ? tokens[row] : n2o[KHOT + (row - NT)];
    float out = 0.f;
    if (f < 2 * NFQ) {
        float x = (float)id / (float)VV;
        int k = (f < NFQ) ? f : f - NFQ;
        float th = x * freqs[k];
        out = (f < NFQ) ? sinf(th) : cosf(th);
    } else if (f < INDIM) {
        int k = f - 2 * NFQ;
        out = (float)((id >> (2 * k)) & 3) / 3.0f;
    }
    g_PHIh[idx] = __float2half_rn(out);
}

__global__ void transT_kernel(const float* __restrict__ W, fp16* __restrict__ oh,
                              int K, int N, int Kpad)
{
    __shared__ float tile[32][33];
    int kb = blockIdx.y << 5, nb = blockIdx.x << 5;
    int tx = threadIdx.x & 31, ty = threadIdx.x >> 5;
    #pragma unroll
    for (int i = ty; i < 32; i += 8) {
        int k = kb + i, n = nb + tx;
        tile[i][tx] = (k < K && n < N) ? W[(size_t)k * N + n] : 0.f;
    }
    __syncthreads();
    #pragma unroll
    for (int i = ty; i < 32; i += 8) {
        int n = nb + i, k = kb + tx;
        if (n < N && k < Kpad)
            oh[(size_t)n * Kpad + k] = __float2half_rn(tile[tx][i]);
    }
}

__global__ void convD_kernel(const float* __restrict__ src, fp16* __restrict__ oh, int n)
{
    int idx = blockIdx.x * blockDim.x + threadIdx.x;
    if (idx >= n) return;
    oh[idx] = __float2half_rn(src[idx]);
}

// latent select (hi plane) + per-row b3 dot. One block per token row.
__global__ void latent_cb3_kernel(const int* __restrict__ tokens, const int* __restrict__ o2n,
                                  const float* __restrict__ b3, int NT)
{
    __shared__ float red[8];
    int t = blockIdx.x;
    int nt = o2n[tokens[t]];
    int j = nt < 0 ? 0 : (nt > KHOT - 1 ? KHOT - 1 : nt);
    bool hot = (nt < KHOT);
    float s = 0.f;
    for (int d = threadIdx.x; d < DD; d += 256) {
        size_t o = (size_t)t * DD + d;
        fp16 vh = hot ? g_Eh[(size_t)j * DD + d] : g_CTh[o];
        g_LATh[o] = vh;
        s += __half2float(vh) * b3[d];
    }
    #pragma unroll
    for (int off = 16; off; off >>= 1) s += __shfl_down_sync(0xFFFFFFFFu, s, off);
    if ((threadIdx.x & 31) == 0) red[threadIdx.x >> 5] = s;
    __syncthreads();
    if (threadIdx.x == 0) {
        float tot = 0.f;
        #pragma unroll
        for (int i = 0; i < 8; i++) tot += red[i];
        g_CB3[t] = tot;
    }
}

// ---------------- launch ----------------
static inline int smemFor(int P) {
    int ar = (P >= 2) ? 2 * A_ROWS : A_ROWS;
    return NSTG * (ar + B_ROWS) * ROWB;
}

extern "C" void kernel_launch(void* const* d_in, const int* in_sizes, int n_in,
                              void* d_out, int out_size)
{
    const int*   tokens   = (const int*)  d_in[0];
    const int*   o2n      = (const int*)  d_in[1];
    const int*   n2o      = (const int*)  d_in[2];
    const float* freqs    = (const float*)d_in[3];
    const float* U        = (const float*)d_in[4];
    const float* Bm       = (const float*)d_in[5];
    const float* W1       = (const float*)d_in[6];
    const float* b1       = (const float*)d_in[7];
    const float* W2       = (const float*)d_in[8];
    const float* b2       = (const float*)d_in[9];
    const float* W3       = (const float*)d_in[10];
    const float* b3       = (const float*)d_in[11];
    const float* tg       = (const float*)d_in[12];
    const float* la       = (const float*)d_in[13];
    const float* out_bias = (const float*)d_in[14];
    float* out = (float*)d_out;

    int NT = in_sizes[0];
    if (NT > NTMAX) NT = NTMAX;
    if (NT <= 0) return;
    int nrows = NT + NCOLD;

    fp16 *pPHIh,*pH1h,*pH2h,*pEh,*pCTh,*pLATh,*pLWh;
    fp16 *pWT1h,*pWT2h,*pWT3h,*pW3Dh,*pBTh,*pUh;
    float *pCB3;
    cudaGetSymbolAddress((void**)&pPHIh, g_PHIh);
    cudaGetSymbolAddress((void**)&pH1h,  g_H1h);
    cudaGetSymbolAddress((void**)&pH2h,  g_H2h);
    cudaGetSymbolAddress((void**)&pEh,   g_Eh);
    cudaGetSymbolAddress((void**)&pCTh,  g_CTh);
    cudaGetSymbolAddress((void**)&pLATh, g_LATh);
    cudaGetSymbolAddress((void**)&pLWh,  g_LWh);
    cudaGetSymbolAddress((void**)&pWT1h, g_WT1h);
    cudaGetSymbolAddress((void**)&pWT2h, g_WT2h);
    cudaGetSymbolAddress((void**)&pWT3h, g_WT3h);
    cudaGetSymbolAddress((void**)&pW3Dh, g_W3Dh);
    cudaGetSymbolAddress((void**)&pBTh,  g_BTh);
    cudaGetSymbolAddress((void**)&pUh,   g_Uh);
    cudaGetSymbolAddress((void**)&pCB3,  g_CB3);

    cudaFuncSetAttribute(mma_gemm<1,false,1>, cudaFuncAttributeMaxDynamicSharedMemorySize, smemFor(1));
    cudaFuncSetAttribute(mma_gemm<2,false,1>, cudaFuncAttributeMaxDynamicSharedMemorySize, smemFor(1));
    cudaFuncSetAttribute(mma_gemm<0,false,1>, cudaFuncAttributeMaxDynamicSharedMemorySize, smemFor(1));
    cudaFuncSetAttribute(mma_gemm<3,true ,1>, cudaFuncAttributeMaxDynamicSharedMemorySize, smemFor(1));
    cudaFuncSetAttribute(mma_gemm<4,true ,1>, cudaFuncAttributeMaxDynamicSharedMemorySize, smemFor(1));

    int mtilesCold = (NCOLD + 127) / 128;
    int ttiles = (NT + 127) / 128;
    int mtilesAll = (nrows + 127) / 128;

    // ---- side stream: U/B conversion + Ehot (1-pass) + W2T/W3T/W3D ----
    cudaEventRecord(g_evA, 0);
    cudaStreamWaitEvent(g_s1, g_evA, 0);
    convD_kernel<<<(KHOT * RHOT + 255) / 256, 256, 0, g_s1>>>(U, pUh, KHOT * RHOT);
    {
        dim3 g4((DD + 31) / 32, (RHOT + 31) / 32);
        transT_kernel<<<g4, 256, 0, g_s1>>>(Bm, pBTh, RHOT, DD, RHOT);
    }
    {
        dim3 g(DD / 128, KHOT / 128);
        mma_gemm<0,false,1><<<g, 256, smemFor(1), g_s1>>>(pUh, nullptr, RHOT, pBTh, RHOT, 0,
            KHOT, DD, RHOT / 32, nullptr, nullptr, nullptr, nullptr, nullptr,
            nullptr, nullptr, pEh, nullptr, DD, 0);
    }
    cudaEventRecord(g_evE, g_s1);
    {
        dim3 g2((HIDD + 31) / 32, (HIDD + 31) / 32);
        transT_kernel<<<g2, 256, 0, g_s1>>>(W2, pWT2h, HIDD, HIDD, HIDD);
        dim3 g3((DD + 31) / 32, (HIDD + 31) / 32);
        transT_kernel<<<g3, 256, 0, g_s1>>>(W3, pWT3h, HIDD, DD, HIDD);
        convD_kernel<<<(HIDD * DD + 255) / 256, 256, 0, g_s1>>>(W3, pW3Dh, HIDD * DD);
    }
    cudaEventRecord(g_evW3, g_s1);

    // ---- main: minimal prefix -> H1 (all rows, single kernel as in R13) ----
    phi_kernel<<<(nrows * INDIMP + 255) / 256, 256>>>(tokens, n2o, freqs, NT, nrows);
    {
        dim3 g1((HIDD + 31) / 32, (INDIMP + 31) / 32);
        transT_kernel<<<g1, 256>>>(W1, pWT1h, INDIM, HIDD, INDIMP);
    }
    {
        dim3 g(HIDD / 128, mtilesAll);
        mma_gemm<1,false,1><<<g, 256, smemFor(1)>>>(pPHIh, nullptr, INDIMP, pWT1h, INDIMP, 0,
            nrows, HIDD, INDIMP / 32, b1, nullptr, nullptr, nullptr, nullptr,
            nullptr, nullptr, pH1h, nullptr, HIDD, 0);
    }

    // ---- fork: H2cold on side stream (W2T already on s1) ----
    cudaEventRecord(g_evH1, 0);
    cudaStreamWaitEvent(g_s1, g_evH1, 0);
    {
        dim3 g(HIDD / 128, mtilesCold);
        mma_gemm<1,false,1><<<g, 256, smemFor(1), g_s1>>>(pH1h + (size_t)NT * HIDD, nullptr, HIDD,
            pWT2h, HIDD, 0,
            NCOLD, HIDD, HIDD / 32, b2, nullptr, nullptr, nullptr, nullptr,
            nullptr, nullptr, pH2h + (size_t)NT * HIDD, nullptr, HIDD, 0);
    }
    cudaEventRecord(g_evB, g_s1);

    // ---- main: token chain (hidden under H2cold) ----
    cudaStreamWaitEvent(0, g_evW3, 0);
    {
        dim3 g(HIDD / 128, ttiles);
        mma_gemm<1,false,1><<<g, 256, smemFor(1)>>>(pH1h, nullptr, HIDD, pWT2h, HIDD, 0,
            NT, HIDD, HIDD / 32, b2, nullptr, nullptr, nullptr, nullptr,
            nullptr, nullptr, pH2h, nullptr, HIDD, 0);
    }
    {
        dim3 g(DD / 128, ttiles);
        mma_gemm<2,false,1><<<g, 256, smemFor(1)>>>(pH2h, nullptr, HIDD, pWT3h, HIDD, 0,
            NT, DD, HIDD / 32, b3, tg, nullptr, nullptr, nullptr,
            nullptr, nullptr, pCTh, nullptr, DD, 0);
    }
    cudaStreamWaitEvent(0, g_evE, 0);
    latent_cb3_kernel<<<NT, 256>>>(tokens, o2n, b3, NT);
    cudaEventRecord(g_evL, 0);
    // LW3 = latent @ W3^T (1-pass)
    {
        dim3 g(HIDD / 128, ttiles);
        mma_gemm<0,false,1><<<g, 256, smemFor(1)>>>(pLATh, nullptr, DD, pW3Dh, DD, 0,
            NT, HIDD, DD / 32, nullptr, nullptr, nullptr, nullptr, nullptr,
            nullptr, nullptr, pLWh, nullptr, HIDD, 0);
    }
    // ---- hot logits on side stream (overlaps cold logits; disjoint columns) ----
    cudaStreamWaitEvent(g_s1, g_evL, 0);
    {
        dim3 g(ttiles, KHOT / 128);
        mma_gemm<3,true,1><<<g, 256, smemFor(1), g_s1>>>(pLATh, nullptr, DD, pEh, DD, 0,
            NT, KHOT, DD / 32, nullptr, nullptr, la, nullptr, n2o,
            out, out_bias, nullptr, nullptr, 0, 0);
    }
    cudaEventRecord(g_evHot, g_s1);

    // ---- join: cold logits (fp32-acc; dominant) ----
    cudaStreamWaitEvent(0, g_evB, 0);
    {
        dim3 g(ttiles, (NCOLD + 127) / 128);
        mma_gemm<4,true,1><<<g, 256, smemFor(1)>>>(pLWh, nullptr, HIDD, pH2h, HIDD, NT,
            NT, NCOLD, HIDD / 32, nullptr, tg, la, pCB3, n2o + KHOT,
            out, out_bias, nullptr, nullptr, 0, 0);
    }
    cudaStreamWaitEvent(0, g_evHot, 0);
}

// round 16
// speedup vs baseline: 1.0201x; 1.0036x over previous
#include <cuda_runtime.h>
#include <cuda_fp16.h>
#include <math.h>
#include <stdint.h>

// ---------------- problem constants ----------------
#define VV     50257
#define DD     1024
#define KHOT   1024
#define RHOT   768
#define HIDD   1024
#define NFQ    48
#define INDIM  104
#define INDIMP 128
#define NTMAX  2048
#define NCOLD  (VV - KHOT)      // 49233
#define NRMAX  (NTMAX + NCOLD)  // 51281

typedef __half fp16;

// ---------------- device scratch (static; no runtime alloc) ----------------
static __device__ fp16 g_PHIh[(size_t)NRMAX * INDIMP];
static __device__ fp16 g_H1h [(size_t)NRMAX * HIDD];
static __device__ fp16 g_H2h [(size_t)NRMAX * HIDD];
static __device__ fp16 g_Eh  [(size_t)KHOT * DD];
static __device__ fp16 g_LATh[(size_t)NTMAX * DD];
static __device__ fp16 g_LWh [(size_t)NTMAX * DD];
static __device__ fp16 g_WT1h[(size_t)HIDD * INDIMP];
static __device__ fp16 g_WT2h[(size_t)HIDD * HIDD];
static __device__ fp16 g_WT3h[(size_t)DD * HIDD];   // W3^T  [D][HID]
static __device__ fp16 g_W3Dh[(size_t)HIDD * DD];   // W3 direct [HID][D]
static __device__ fp16 g_BTh [(size_t)DD * RHOT];
static __device__ fp16 g_Uh  [(size_t)KHOT * RHOT];
static __device__ float g_CB3[NTMAX];

// ---------------- static streams/events (created at load; no device mem) ---
static cudaStream_t g_s1;
static cudaEvent_t  g_evA, g_evE, g_evH1, g_evB, g_evL, g_evHot, g_evW3;
static struct _AsyncInit {
    _AsyncInit() {
        cudaStreamCreateWithFlags(&g_s1, cudaStreamNonBlocking);
        cudaEventCreateWithFlags(&g_evA,   cudaEventDisableTiming);
        cudaEventCreateWithFlags(&g_evE,   cudaEventDisableTiming);
        cudaEventCreateWithFlags(&g_evH1,  cudaEventDisableTiming);
        cudaEventCreateWithFlags(&g_evB,   cudaEventDisableTiming);
        cudaEventCreateWithFlags(&g_evL,   cudaEventDisableTiming);
        cudaEventCreateWithFlags(&g_evHot, cudaEventDisableTiming);
        cudaEventCreateWithFlags(&g_evW3,  cudaEventDisableTiming);
    }
} g_asyncInit;

// ---------------- helpers ----------------
__device__ __forceinline__ void hsplit(float x, fp16& h, fp16& l) {
    h = __float2half_rn(x);
    l = __float2half_rn(x - __half2float(h));
}
__device__ __forceinline__ float gelu_exact(float x) {
    return 0.5f * x * (1.0f + erff(x * 0.7071067811865476f));
}
__device__ __forceinline__ uint32_t s2u(const void* p) {
    uint32_t a;
    asm("{ .reg .u64 t; cvta.to.shared.u64 t, %1; cvt.u32.u64 %0, t; }" : "=r"(a) : "l"(p));
    return a;
}
__device__ __forceinline__ void ldsm4(uint32_t* r, uint32_t addr) {
    asm volatile("ldmatrix.sync.aligned.m8n8.x4.shared.b16 {%0,%1,%2,%3}, [%4];"
                 : "=r"(r[0]), "=r"(r[1]), "=r"(r[2]), "=r"(r[3]) : "r"(addr));
}
__device__ __forceinline__ void mma16816(float* c, const uint32_t* a, const uint32_t* b) {
    asm volatile("mma.sync.aligned.m16n8k16.row.col.f32.f16.f16.f32 "
                 "{%0,%1,%2,%3}, {%4,%5,%6,%7}, {%8,%9}, {%0,%1,%2,%3};"
                 : "+f"(c[0]), "+f"(c[1]), "+f"(c[2]), "+f"(c[3])
                 : "r"(a[0]), "r"(a[1]), "r"(a[2]), "r"(a[3]), "r"(b[0]), "r"(b[1]));
}
__device__ __forceinline__ void cpa16(uint32_t dst, const void* src) {
    asm volatile("cp.async.cg.shared.global [%0], [%1], 16;" :: "r"(dst), "l"(src) : "memory");
}

// ---------------- SMEM geometry ----------------
#define ROWB   80
#define A_ROWS 128
#define B_ROWS 128
#define NSTG   3

// ---------------- the mma.sync GEMM (BM=128, BN=128, BK=32, occ 2) ---------
// PASSES: 1 = ah*bh; 2 = + al*bh (A split).
// MODE 0/1/2: C hi plane (+lo for rows < loRows)
// MODE 3: out[gm, colmap[gn]] = acc * exp(*pLA) + out_bias[v]
// MODE 4: out[gm, colmap[gn]] = (acc + rowc[gm]) * exp(*pLA)*(*pTG) + out_bias[v]
template<int MODE, bool SWAPXY, int PASSES>
__global__ void __launch_bounds__(256, 2)
mma_gemm(const fp16* __restrict__ Ah, const fp16* __restrict__ Al, int lda,
         const fp16* __restrict__ Bh, int ldb, int browOff,
         int M, int N, int KT,
         const float* __restrict__ bias, const float* __restrict__ pTG,
         const float* __restrict__ pLA, const float* __restrict__ rowc,
         const int* __restrict__ colmap,
         float* __restrict__ outF, const float* __restrict__ out_bias,
         fp16* __restrict__ Chi, fp16* __restrict__ Clo, int ldc, int loRows)
{
    constexpr int AR = (PASSES >= 2) ? 2 * A_ROWS : A_ROWS;
    constexpr int BR = B_ROWS;
    constexpr int STAGE = (AR + BR) * ROWB;
    constexpr int CH = (AR + BR) / 64;
    constexpr int O_AL = A_ROWS * ROWB;
    constexpr int O_BH = AR * ROWB;

    extern __shared__ char smem[];
    const uint32_t sbase = s2u(smem);
    const int tid = threadIdx.x;
    const int bm = (SWAPXY ? blockIdx.x : blockIdx.y) << 7;
    const int bn = (SWAPXY ? blockIdx.y : blockIdx.x) << 7;

    float acc[2][8][4];
    #pragma unroll
    for (int i = 0; i < 2; i++)
        #pragma unroll
        for (int j = 0; j < 8; j++)
            #pragma unroll
            for (int q = 0; q < 4; q++) acc[i][j][q] = 0.f;

    auto load_stage = [&](int s, int kt) {
        const int k0 = kt << 5;
        const uint32_t stg = sbase + s * STAGE;
        #pragma unroll
        for (int i = 0; i < CH; i++) {
            int idx = tid + (i << 8);
            int row = idx >> 2;
            int seg = idx & 3;
            uint32_t daddr = stg + row * ROWB + (seg << 4);
            const fp16* src;
            bool valid;
            if (row < AR) {
                int plane = (PASSES >= 2) ? (row >> 7) : 0;
                int r = row & (A_ROWS - 1);
                int gm = bm + r;
                valid = gm < M;
                src = (plane ? Al : Ah) + (size_t)gm * lda + k0 + (seg << 3);
            } else {
                int r = row - AR;
                int gn = bn + r;
                valid = gn < N;
                src = Bh + (size_t)(gn + browOff) * ldb + k0 + (seg << 3);
            }
            if (valid) cpa16(daddr, src);
            else {
                asm volatile("st.shared.v4.b32 [%0], {%1,%1,%1,%1};" :: "r"(daddr), "r"(0u) : "memory");
            }
        }
        asm volatile("cp.async.commit_group;" ::: "memory");
    };

    const int lane = tid & 31, wid = tid >> 5;
    const int wm = wid & 3;        // 4 M-subtiles of 32
    const int wn = wid >> 2;       // 2 N-subtiles of 64

    load_stage(0, 0);
    if (KT > 1) load_stage(1, 1);

    for (int kt = 0; kt < KT; kt++) {
        int s = kt % NSTG;
        if (kt + 1 < KT) asm volatile("cp.async.wait_group 1;" ::: "memory");
        else             asm volatile("cp.async.wait_group 0;" ::: "memory");
        __syncthreads();
        if (kt + 2 < KT) load_stage((kt + 2) % NSTG, kt + 2);

        const uint32_t stg = sbase + s * STAGE;
        #pragma unroll
        for (int kk = 0; kk < 2; kk++) {
            uint32_t bh[8][2];
            #pragma unroll
            for (int bi = 0; bi < 4; bi++) {
                int row = wn * 64 + bi * 16 + (lane & 7) + ((lane >> 4) << 3);
                int kb  = kk * 16 + (((lane >> 3) & 1) << 3);
                uint32_t bd = stg + O_BH + row * ROWB + kb * 2;
                uint32_t t[4];
                ldsm4(t, bd);
                bh[bi*2][0] = t[0]; bh[bi*2][1] = t[1];
                bh[bi*2+1][0] = t[2]; bh[bi*2+1][1] = t[3];
            }
            #pragma unroll
            for (int mi = 0; mi < 2; mi++) {
                int row = wm * 32 + mi * 16 + (lane & 15);
                int kb  = kk * 16 + ((lane >> 4) << 3);
                uint32_t ad = stg + row * ROWB + kb * 2;
                uint32_t ah[4], al[4];
                ldsm4(ah, ad);
                if (PASSES >= 2) ldsm4(al, ad + O_AL);
                #pragma unroll
                for (int ni = 0; ni < 8; ni++) {
                    mma16816(acc[mi][ni], ah, bh[ni]);
                    if (PASSES >= 2) mma16816(acc[mi][ni], al, bh[ni]);
                }
            }
        }
        __syncthreads();
    }

    // ---------------- epilogue ----------------
    float s1 = 1.f;
    if (MODE == 2) s1 = *pTG;
    if (MODE == 3) s1 = expf(*pLA);
    if (MODE == 4) s1 = expf(*pLA) * (*pTG);

    #pragma unroll
    for (int mi = 0; mi < 2; mi++) {
        #pragma unroll
        for (int ni = 0; ni < 8; ni++) {
            int gm0 = bm + wm * 32 + mi * 16 + (lane >> 2);
            int gn0 = bn + wn * 64 + ni * 8 + ((lane & 3) << 1);
            #pragma unroll
            for (int h = 0; h < 2; h++) {
                int gm = gm0 + h * 8;
                if (gm >= M) continue;
                float v0 = acc[mi][ni][h * 2 + 0];
                float v1 = acc[mi][ni][h * 2 + 1];
                if (MODE <= 2) {
                    if (gn0 >= N) continue;
                    if (MODE == 1) {
                        v0 = gelu_exact(v0 + bias[gn0]);
                        v1 = gelu_exact(v1 + bias[gn0 + 1]);
                    } else if (MODE == 2) {
                        v0 = (v0 + bias[gn0]) * s1;
                        v1 = (v1 + bias[gn0 + 1]) * s1;
                    }
                    fp16 h0, l0, h1, l1;
                    hsplit(v0, h0, l0); hsplit(v1, h1, l1);
                    size_t off = (size_t)gm * ldc + gn0;
                    *(__half2*)(Chi + off) = __halves2half2(h0, h1);
                    if (gm < loRows)
                        *(__half2*)(Clo + off) = __halves2half2(l0, l1);
                } else {
                    float rc = (MODE == 4) ? rowc[gm] : 0.f;
                    if (gn0 < N) {
                        int v = colmap[gn0];
                        v = v < 0 ? 0 : (v > VV - 1 ? VV - 1 : v);
                        outF[(size_t)gm * VV + v] = (v0 + rc) * s1 + out_bias[v];
                    }
                    if (gn0 + 1 < N) {
                        int v = colmap[gn0 + 1];
                        v = v < 0 ? 0 : (v > VV - 1 ? VV - 1 : v);
                        outF[(size_t)gm * VV + v] = (v1 + rc) * s1 + out_bias[v];
                    }
                }
            }
        }
    }
}

// ---------------- prep kernels ----------------
__global__ void phi_kernel(const int* __restrict__ tokens, const int* __restrict__ n2o,
                           const float* __restrict__ freqs, int NT, int nrows)
{
    int idx = blockIdx.x * blockDim.x + threadIdx.x;
    if (idx >= nrows * INDIMP) return;
    int row = idx >> 7;
    int f = idx & 127;
    int id = (row < NT) ? tokens[row] : n2o[KHOT + (row - NT)];
    float out = 0.f;
    if (f < 2 * NFQ) {
        float x = (float)id / (float)VV;
        int k = (f < NFQ) ? f : f - NFQ;
        float th = x * freqs[k];
        out = (f < NFQ) ? sinf(th) : cosf(th);
    } else if (f < INDIM) {
        int k = f - 2 * NFQ;
        out = (float)((id >> (2 * k)) & 3) / 3.0f;
    }
    g_PHIh[idx] = __float2half_rn(out);
}

__global__ void transT_kernel(const float* __restrict__ W, fp16* __restrict__ oh,
                              int K, int N, int Kpad)
{
    __shared__ float tile[32][33];
    int kb = blockIdx.y << 5, nb = blockIdx.x << 5;
    int tx = threadIdx.x & 31, ty = threadIdx.x >> 5;
    #pragma unroll
    for (int i = ty; i < 32; i += 8) {
        int k = kb + i, n = nb + tx;
        tile[i][tx] = (k < K && n < N) ? W[(size_t)k * N + n] : 0.f;
    }
    __syncthreads();
    #pragma unroll
    for (int i = ty; i < 32; i += 8) {
        int n = nb + i, k = kb + tx;
        if (n < N && k < Kpad)
            oh[(size_t)n * Kpad + k] = __float2half_rn(tile[tx][i]);
    }
}

__global__ void convD_kernel(const float* __restrict__ src, fp16* __restrict__ oh, int n)
{
    int idx = blockIdx.x * blockDim.x + threadIdx.x;
    if (idx >= n) return;
    oh[idx] = __float2half_rn(src[idx]);
}

// LATh already holds CT (cold) values; overwrite hot rows from Eh, compute cb3.
__global__ void hotfix_cb3_kernel(const int* __restrict__ tokens, const int* __restrict__ o2n,
                                  const float* __restrict__ b3, int NT)
{
    __shared__ float red[8];
    int t = blockIdx.x;
    int nt = o2n[tokens[t]];
    int j = nt < 0 ? 0 : (nt > KHOT - 1 ? KHOT - 1 : nt);
    bool hot = (nt < KHOT);
    float s = 0.f;
    for (int d = threadIdx.x; d < DD; d += 256) {
        size_t o = (size_t)t * DD + d;
        fp16 vh;
        if (hot) {
            vh = g_Eh[(size_t)j * DD + d];
            g_LATh[o] = vh;
        } else {
            vh = g_LATh[o];
        }
        s += __half2float(vh) * b3[d];
    }
    #pragma unroll
    for (int off = 16; off; off >>= 1) s += __shfl_down_sync(0xFFFFFFFFu, s, off);
    if ((threadIdx.x & 31) == 0) red[threadIdx.x >> 5] = s;
    __syncthreads();
    if (threadIdx.x == 0) {
        float tot = 0.f;
        #pragma unroll
        for (int i = 0; i < 8; i++) tot += red[i];
        g_CB3[t] = tot;
    }
}

// ---------------- launch ----------------
static inline int smemFor(int P) {
    int ar = (P >= 2) ? 2 * A_ROWS : A_ROWS;
    return NSTG * (ar + B_ROWS) * ROWB;
}

extern "C" void kernel_launch(void* const* d_in, const int* in_sizes, int n_in,
                              void* d_out, int out_size)
{
    const int*   tokens   = (const int*)  d_in[0];
    const int*   o2n      = (const int*)  d_in[1];
    const int*   n2o      = (const int*)  d_in[2];
    const float* freqs    = (const float*)d_in[3];
    const float* U        = (const float*)d_in[4];
    const float* Bm       = (const float*)d_in[5];
    const float* W1       = (const float*)d_in[6];
    const float* b1       = (const float*)d_in[7];
    const float* W2       = (const float*)d_in[8];
    const float* b2       = (const float*)d_in[9];
    const float* W3       = (const float*)d_in[10];
    const float* b3       = (const float*)d_in[11];
    const float* tg       = (const float*)d_in[12];
    const float* la       = (const float*)d_in[13];
    const float* out_bias = (const float*)d_in[14];
    float* out = (float*)d_out;

    int NT = in_sizes[0];
    if (NT > NTMAX) NT = NTMAX;
    if (NT <= 0) return;
    int nrows = NT + NCOLD;

    fp16 *pPHIh,*pH1h,*pH2h,*pEh,*pLATh,*pLWh;
    fp16 *pWT1h,*pWT2h,*pWT3h,*pW3Dh,*pBTh,*pUh;
    float *pCB3;
    cudaGetSymbolAddress((void**)&pPHIh, g_PHIh);
    cudaGetSymbolAddress((void**)&pH1h,  g_H1h);
    cudaGetSymbolAddress((void**)&pH2h,  g_H2h);
    cudaGetSymbolAddress((void**)&pEh,   g_Eh);
    cudaGetSymbolAddress((void**)&pLATh, g_LATh);
    cudaGetSymbolAddress((void**)&pLWh,  g_LWh);
    cudaGetSymbolAddress((void**)&pWT1h, g_WT1h);
    cudaGetSymbolAddress((void**)&pWT2h, g_WT2h);
    cudaGetSymbolAddress((void**)&pWT3h, g_WT3h);
    cudaGetSymbolAddress((void**)&pW3Dh, g_W3Dh);
    cudaGetSymbolAddress((void**)&pBTh,  g_BTh);
    cudaGetSymbolAddress((void**)&pUh,   g_Uh);
    cudaGetSymbolAddress((void**)&pCB3,  g_CB3);

    cudaFuncSetAttribute(mma_gemm<1,false,1>, cudaFuncAttributeMaxDynamicSharedMemorySize, smemFor(1));
    cudaFuncSetAttribute(mma_gemm<2,false,1>, cudaFuncAttributeMaxDynamicSharedMemorySize, smemFor(1));
    cudaFuncSetAttribute(mma_gemm<0,false,1>, cudaFuncAttributeMaxDynamicSharedMemorySize, smemFor(1));
    cudaFuncSetAttribute(mma_gemm<3,true ,1>, cudaFuncAttributeMaxDynamicSharedMemorySize, smemFor(1));
    cudaFuncSetAttribute(mma_gemm<4,true ,1>, cudaFuncAttributeMaxDynamicSharedMemorySize, smemFor(1));

    int mtilesCold = (NCOLD + 127) / 128;
    int ttiles = (NT + 127) / 128;
    int mtilesAll = (nrows + 127) / 128;

    // ---- side stream: U/B conversion + Ehot (1-pass) + W2T/W3T/W3D ----
    cudaEventRecord(g_evA, 0);
    cudaStreamWaitEvent(g_s1, g_evA, 0);
    convD_kernel<<<(KHOT * RHOT + 255) / 256, 256, 0, g_s1>>>(U, pUh, KHOT * RHOT);
    {
        dim3 g4((DD + 31) / 32, (RHOT + 31) / 32);
        transT_kernel<<<g4, 256, 0, g_s1>>>(Bm, pBTh, RHOT, DD, RHOT);
    }
    {
        dim3 g(DD / 128, KHOT / 128);
        mma_gemm<0,false,1><<<g, 256, smemFor(1), g_s1>>>(pUh, nullptr, RHOT, pBTh, RHOT, 0,
            KHOT, DD, RHOT / 32, nullptr, nullptr, nullptr, nullptr, nullptr,
            nullptr, nullptr, pEh, nullptr, DD, 0);
    }
    cudaEventRecord(g_evE, g_s1);
    {
        dim3 g2((HIDD + 31) / 32, (HIDD + 31) / 32);
        transT_kernel<<<g2, 256, 0, g_s1>>>(W2, pWT2h, HIDD, HIDD, HIDD);
        dim3 g3((DD + 31) / 32, (HIDD + 31) / 32);
        transT_kernel<<<g3, 256, 0, g_s1>>>(W3, pWT3h, HIDD, DD, HIDD);
        convD_kernel<<<(HIDD * DD + 255) / 256, 256, 0, g_s1>>>(W3, pW3Dh, HIDD * DD);
    }
    cudaEventRecord(g_evW3, g_s1);

    // ---- main: minimal prefix -> H1 (all rows, single kernel) ----
    phi_kernel<<<(nrows * INDIMP + 255) / 256, 256>>>(tokens, n2o, freqs, NT, nrows);
    {
        dim3 g1((HIDD + 31) / 32, (INDIMP + 31) / 32);
        transT_kernel<<<g1, 256>>>(W1, pWT1h, INDIM, HIDD, INDIMP);
    }
    {
        dim3 g(HIDD / 128, mtilesAll);
        mma_gemm<1,false,1><<<g, 256, smemFor(1)>>>(pPHIh, nullptr, INDIMP, pWT1h, INDIMP, 0,
            nrows, HIDD, INDIMP / 32, b1, nullptr, nullptr, nullptr, nullptr,
            nullptr, nullptr, pH1h, nullptr, HIDD, 0);
    }

    // ---- fork: H2cold on side stream (W2T already on s1) ----
    cudaEventRecord(g_evH1, 0);
    cudaStreamWaitEvent(g_s1, g_evH1, 0);
    {
        dim3 g(HIDD / 128, mtilesCold);
        mma_gemm<1,false,1><<<g, 256, smemFor(1), g_s1>>>(pH1h + (size_t)NT * HIDD, nullptr, HIDD,
            pWT2h, HIDD, 0,
            NCOLD, HIDD, HIDD / 32, b2, nullptr, nullptr, nullptr, nullptr,
            nullptr, nullptr, pH2h + (size_t)NT * HIDD, nullptr, HIDD, 0);
    }
    cudaEventRecord(g_evB, g_s1);

    // ---- main: token chain (hidden under H2cold) ----
    cudaStreamWaitEvent(0, g_evW3, 0);
    {
        dim3 g(HIDD / 128, ttiles);
        mma_gemm<1,false,1><<<g, 256, smemFor(1)>>>(pH1h, nullptr, HIDD, pWT2h, HIDD, 0,
            NT, HIDD, HIDD / 32, b2, nullptr, nullptr, nullptr, nullptr,
            nullptr, nullptr, pH2h, nullptr, HIDD, 0);
    }
    // CT written DIRECTLY into LATh (cold-token values; hot rows fixed next)
    {
        dim3 g(DD / 128, ttiles);
        mma_gemm<2,false,1><<<g, 256, smemFor(1)>>>(pH2h, nullptr, HIDD, pWT3h, HIDD, 0,
            NT, DD, HIDD / 32, b3, tg, nullptr, nullptr, nullptr,
            nullptr, nullptr, pLATh, nullptr, DD, 0);
    }
    cudaStreamWaitEvent(0, g_evE, 0);
    hotfix_cb3_kernel<<<NT, 256>>>(tokens, o2n, b3, NT);
    cudaEventRecord(g_evL, 0);
    // LW3 = latent @ W3^T (1-pass)
    {
        dim3 g(HIDD / 128, ttiles);
        mma_gemm<0,false,1><<<g, 256, smemFor(1)>>>(pLATh, nullptr, DD, pW3Dh, DD, 0,
            NT, HIDD, DD / 32, nullptr, nullptr, nullptr, nullptr, nullptr,
            nullptr, nullptr, pLWh, nullptr, HIDD, 0);
    }
    // ---- hot logits on side stream (overlaps cold logits; disjoint columns) ----
    cudaStreamWaitEvent(g_s1, g_evL, 0);
    {
        dim3 g(ttiles, KHOT / 128);
        mma_gemm<3,true,1><<<g, 256, smemFor(1), g_s1>>>(pLATh, nullptr, DD, pEh, DD, 0,
            NT, KHOT, DD / 32, nullptr, nullptr, la, nullptr, n2o,
            out, out_bias, nullptr, nullptr, 0, 0);
    }
    cudaEventRecord(g_evHot, g_s1);

    // ---- join: cold logits (fp32-acc; dominant) ----
    cudaStreamWaitEvent(0, g_evB, 0);
    {
        dim3 g(ttiles, (NCOLD + 127) / 128);
        mma_gemm<4,true,1><<<g, 256, smemFor(1)>>>(pLWh, nullptr, HIDD, pH2h, HIDD, NT,
            NT, NCOLD, HIDD / 32, nullptr, tg, la, pCB3, n2o + KHOT,
            out, out_bias, nullptr, nullptr, 0, 0);
    }
    cudaStreamWaitEvent(0, g_evHot, 0);
}